// round 12
// baseline (speedup 1.0000x reference)
#include <cuda_runtime.h>
#include <cuda_fp16.h>
#include <cstdint>

// Problem dims
#define NB   512
#define TQ   128
#define CD   384
#define HD   64
#define SCALE 0.4082482904638631f   // 6^-0.5

// W pre-split: fp16 hi/lo pair words, layout [n=192][kpair=192]
__device__ __align__(16) uint32_t g_whi[192*192];
__device__ __align__(16) uint32_t g_wlo[192*192];

// ---------------- helpers ----------------
__device__ __forceinline__ void mma_f16(float* d, const uint32_t* a,
                                        uint32_t b0, uint32_t b1)
{
    asm("mma.sync.aligned.m16n8k16.row.col.f32.f16.f16.f32 "
        "{%0,%1,%2,%3}, {%4,%5,%6,%7}, {%8,%9}, {%0,%1,%2,%3};"
        : "+f"(d[0]), "+f"(d[1]), "+f"(d[2]), "+f"(d[3])
        : "r"(a[0]), "r"(a[1]), "r"(a[2]), "r"(a[3]), "r"(b0), "r"(b1));
}
__device__ __forceinline__ void mma_f16_k8(float* d, uint32_t a0, uint32_t a1,
                                           uint32_t b0)
{
    asm("mma.sync.aligned.m16n8k8.row.col.f32.f16.f16.f32 "
        "{%0,%1,%2,%3}, {%4,%5}, {%6}, {%0,%1,%2,%3};"
        : "+f"(d[0]), "+f"(d[1]), "+f"(d[2]), "+f"(d[3])
        : "r"(a0), "r"(a1), "r"(b0));
}
#define LDM4(r, a) \
    asm volatile("ldmatrix.sync.aligned.m8n8.x4.shared.b16 {%0,%1,%2,%3}, [%4];" \
        : "=r"((r)[0]), "=r"((r)[1]), "=r"((r)[2]), "=r"((r)[3]) : "r"(a))
#define LDM4T(r, a) \
    asm volatile("ldmatrix.sync.aligned.m8n8.x4.trans.shared.b16 {%0,%1,%2,%3}, [%4];" \
        : "=r"((r)[0]), "=r"((r)[1]), "=r"((r)[2]), "=r"((r)[3]) : "r"(a))
#define BARP(id) asm volatile("bar.sync %0, 64;" :: "r"(id) : "memory")

__device__ __forceinline__ void splith(float e0, float e1,
                                       uint32_t& h, uint32_t& l)
{
    __half2 H = __floats2half2_rn(e0, e1);
    float f0 = __low2float(H), f1 = __high2float(H);
    __half2 L = __floats2half2_rn(e0 - f0, e1 - f1);
    h = *(uint32_t*)&H;
    l = *(uint32_t*)&L;
}
__device__ __forceinline__ void cp16(uint32_t s, const void* g) {
    asm volatile("cp.async.cg.shared.global [%0], [%1], 16;" :: "r"(s), "l"(g));
}

// ============================================================================
// Kernel 0: split W -> fp16 hi/lo pair words, [n=192][kpair=192]
// ============================================================================
__global__ __launch_bounds__(256) void wsplit_kernel(
    const float* __restrict__ Wq, const float* __restrict__ Wk,
    const float* __restrict__ Wv)
{
    int idx = blockIdx.x * 256 + threadIdx.x;
    if (idx >= 192 * 192) return;
    int kp = idx / 192, n = idx % 192;        // n fastest -> coalesced reads
    const float* W = (n < 64) ? Wq : (n < 128) ? Wk : Wv;
    int c = n & 63;
    float e0 = W[(size_t)(2 * kp) * HD + c];
    float e1 = W[(size_t)(2 * kp + 1) * HD + c];
    uint32_t h, l;
    splith(e0, e1, h, l);
    g_whi[n * 192 + kp] = h;
    g_wlo[n * 192 + kp] = l;
}

// ============================================================================
// Fused kernel: one CTA per batch (512 threads, 16 warps).
// Proj: A fragments DIRECT from global (no A smem); B triple-buffered cp.async.
// Attn: identical to the R9 best (pairwise barriers, normalized P).
// ============================================================================
// smem word offsets
#define PB_H  0          // [3][192*20]
#define PB_L  11520
#define AQ_H  23040      // [128][36] each
#define AQ_L  27648
#define AK_H  32256
#define AK_L  36864
#define AV_H  41472
#define AV_L  46080
// overlaid on dead proj B buffers:
#define PMX   0          // float [2][128]
#define PSUM  256        // float [2][128]
#define OPART 512        // float [128][66]
#define FU_SMEM (50688 * 4)   // 202,752 B

__global__ __launch_bounds__(512) void fused_kernel(
    const float* __restrict__ x, float* __restrict__ out)
{
    extern __shared__ uint32_t sw[];
    float* smf = (float*)sw;
    const uint32_t sb = (uint32_t)__cvta_generic_to_shared(sw);
    const int tid = threadIdx.x, b = blockIdx.x;
    const int lane = tid & 31, wid = tid >> 5;
    const int gr = lane >> 2, tg = lane & 3;

    // ------------------------- Phase 1: projection -------------------------
    const int wm = (wid & 3) * 32;
    const int wn = (wid >> 2) * 48;

    // B loader precompute: 1536 16B-chunks, 3 per thread
    const uint32_t* bl_src[3];
    uint32_t bl_dstw[3];
    #pragma unroll
    for (int j = 0; j < 3; j++) {
        int id = tid + j * 512;
        int hi = (id < 768);
        int i = hi ? id : id - 768;
        int bn = i >> 2, bch = i & 3;
        bl_src[j] = (hi ? g_whi : g_wlo) + bn * 192 + bch * 4;
        bl_dstw[j] = (hi ? PB_H : PB_L) + bn * 20 + bch * 4;
    }
#define PLOADB(buf, t) do {                                                    \
    _Pragma("unroll")                                                          \
    for (int _j = 0; _j < 3; _j++)                                             \
        cp16(sb + (bl_dstw[_j] + (buf) * 3840) * 4, bl_src[_j] + (t) * 16);    \
    asm volatile("cp.async.commit_group;" ::: "memory");                       \
} while (0)

    // ldmatrix lane address for B fragments
    const int a_r = (lane & 7) + ((lane >> 3) & 1) * 8;
    const int a_c = ((lane >> 4) & 1) * 4;
    const int b_r = lane & 7;
    const int b_half = (lane >> 3) & 1;
    const int b_nt = (lane >> 4) & 1;
    uint32_t boff[3];
    #pragma unroll
    for (int p = 0; p < 3; p++)
        boff[p] = ((wn + (2 * p + b_nt) * 8 + b_r) * 20 + b_half * 4) * 4;

    // direct-A base pointer: this thread's fragment rows/cols
    const float* aRow = x + ((size_t)b * 128 + wm + gr) * CD + 2 * tg;

    float acc[2][6][4];
    #pragma unroll
    for (int mt = 0; mt < 2; mt++)
        #pragma unroll
        for (int nt = 0; nt < 6; nt++)
            #pragma unroll
            for (int i = 0; i < 4; i++) acc[mt][nt][i] = 0.f;

    PLOADB(0, 0);
    PLOADB(1, 1);

    #pragma unroll 3
    for (int t = 0; t < 12; t++) {
        const int buf = t % 3;
        if (t < 11) {
            asm volatile("cp.async.wait_group 1;" ::: "memory");
        } else {
            asm volatile("cp.async.wait_group 0;" ::: "memory");
        }
        __syncthreads();
        if (t < 10) PLOADB((t + 2) % 3, t + 2);

        const uint32_t bBH = sb + (PB_H + buf * 3840) * 4;
        const uint32_t bBL = sb + (PB_L + buf * 3840) * 4;
        #pragma unroll
        for (int kk = 0; kk < 2; kk++) {
            const int c = t * 32 + kk * 16;
            // A fragments direct from global (L1-cached, 4x reuse in wm-group)
            float2 x00 = *(const float2*)(aRow + c);
            float2 x10 = *(const float2*)(aRow + 8 * CD + c);
            float2 x01 = *(const float2*)(aRow + c + 8);
            float2 x11 = *(const float2*)(aRow + 8 * CD + c + 8);
            float2 y00 = *(const float2*)(aRow + 16 * CD + c);
            float2 y10 = *(const float2*)(aRow + 24 * CD + c);
            float2 y01 = *(const float2*)(aRow + 16 * CD + c + 8);
            float2 y11 = *(const float2*)(aRow + 24 * CD + c + 8);
            uint32_t AH0[4], AL0[4], AH1[4], AL1[4];
            splith(x00.x, x00.y, AH0[0], AL0[0]);
            splith(x10.x, x10.y, AH0[1], AL0[1]);
            splith(x01.x, x01.y, AH0[2], AL0[2]);
            splith(x11.x, x11.y, AH0[3], AL0[3]);
            splith(y00.x, y00.y, AH1[0], AL1[0]);
            splith(y10.x, y10.y, AH1[1], AL1[1]);
            splith(y01.x, y01.y, AH1[2], AL1[2]);
            splith(y11.x, y11.y, AH1[3], AL1[3]);
            #pragma unroll
            for (int p = 0; p < 3; p++) {
                uint32_t BH[4], BL[4];
                LDM4(BH, bBH + boff[p] + kk * 32);
                LDM4(BL, bBL + boff[p] + kk * 32);
                mma_f16(acc[0][2*p],   AH0, BH[0], BH[1]);
                mma_f16(acc[1][2*p],   AH1, BH[0], BH[1]);
                mma_f16(acc[0][2*p+1], AH0, BH[2], BH[3]);
                mma_f16(acc[1][2*p+1], AH1, BH[2], BH[3]);
                mma_f16(acc[0][2*p],   AH0, BL[0], BL[1]);
                mma_f16(acc[1][2*p],   AH1, BL[0], BL[1]);
                mma_f16(acc[0][2*p+1], AH0, BL[2], BL[3]);
                mma_f16(acc[1][2*p+1], AH1, BL[2], BL[3]);
                mma_f16(acc[0][2*p],   AL0, BH[0], BH[1]);
                mma_f16(acc[1][2*p],   AL1, BH[0], BH[1]);
                mma_f16(acc[0][2*p+1], AL0, BH[2], BH[3]);
                mma_f16(acc[1][2*p+1], AL1, BH[2], BH[3]);
            }
        }
    }

    // ---- proj epilogue: write Q (xSCALE) / K / V into attn smem ----
    #pragma unroll
    for (int nt = 0; nt < 6; nt++) {
        int n = wn + nt * 8;
        int base_h = (n < 64) ? AQ_H : (n < 128) ? AK_H : AV_H;
        int base_l = (n < 64) ? AQ_L : (n < 128) ? AK_L : AV_L;
        float sc = (n < 64) ? SCALE : 1.0f;
        int pidx = ((n & 63) >> 1) + tg;
        #pragma unroll
        for (int mt = 0; mt < 2; mt++) {
            int ra = wm + mt * 16 + gr;
            int rb = ra + 8;
            uint32_t h, l;
            splith(acc[mt][nt][0] * sc, acc[mt][nt][1] * sc, h, l);
            sw[base_h + ra * 36 + pidx] = h;
            sw[base_l + ra * 36 + pidx] = l;
            splith(acc[mt][nt][2] * sc, acc[mt][nt][3] * sc, h, l);
            sw[base_h + rb * 36 + pidx] = h;
            sw[base_l + rb * 36 + pidx] = l;
        }
    }
    __syncthreads();

    // ------------------------- Phase 2: attention (R9) -------------------------
    const int pairIdx = wid & 7;
    const int half = wid >> 3;
    const int tt = (pairIdx < 4) ? pairIdx : 11 - pairIdx;
    const int t0 = 16 * tt;
    const int r0 = t0 + gr, r1 = r0 + 8;
    const int barid = 1 + pairIdx;

    const uint32_t q_byte = ((t0 + a_r) * 36 + a_c) * 4;
    const uint32_t k_byte = (((half + 2 * b_nt) * 8 + b_r) * 36 + 4 * b_half) * 4;
    const int vg = lane >> 3;
    const uint32_t v_byte = (((half + 2 * (vg & 1)) * 8 + (lane & 7)) * 36
                             + ((vg >> 1) ? 4 : 0)) * 4;

    float sacc[8][4];
    #pragma unroll
    for (int j = 0; j < 8; j++)
        #pragma unroll
        for (int i = 0; i < 4; i++) sacc[j][i] = 0.f;

    #pragma unroll
    for (int kk = 0; kk < 4; kk++) {
        uint32_t AH[4], AL[4];
        LDM4(AH, sb + AQ_H * 4 + q_byte + kk * 32);
        LDM4(AL, sb + AQ_L * 4 + q_byte + kk * 32);
        #pragma unroll
        for (int jp = 0; jp < 4; jp++) {
            int j0 = 2 * jp, j1 = 2 * jp + 1;
            if (j0 <= tt) {
                uint32_t KH[4], KL[4];
                LDM4(KH, sb + AK_H * 4 + k_byte + jp * 4608 + kk * 32);
                LDM4(KL, sb + AK_L * 4 + k_byte + jp * 4608 + kk * 32);
                mma_f16(sacc[j0], AH, KH[0], KH[1]);
                mma_f16(sacc[j0], AH, KL[0], KL[1]);
                mma_f16(sacc[j0], AL, KH[0], KH[1]);
                if (j1 <= tt) {
                    mma_f16(sacc[j1], AH, KH[2], KH[3]);
                    mma_f16(sacc[j1], AH, KL[2], KL[3]);
                    mma_f16(sacc[j1], AL, KH[2], KH[3]);
                }
            }
        }
    }

    const float NEG = __int_as_float(0xff800000);
    float mx0 = NEG, mx1 = NEG;
    #pragma unroll
    for (int j = 0; j < 8; j++) {
        if (j <= tt) {
            int c = (2 * j + half) * 8 + 2 * tg;
            float v0 = (c     <= r0) ? sacc[j][0] : NEG;   // SCALE already in Q
            float v1 = (c + 1 <= r0) ? sacc[j][1] : NEG;
            float v2 = (c     <= r1) ? sacc[j][2] : NEG;
            float v3 = (c + 1 <= r1) ? sacc[j][3] : NEG;
            sacc[j][0] = v0; sacc[j][1] = v1; sacc[j][2] = v2; sacc[j][3] = v3;
            mx0 = fmaxf(mx0, fmaxf(v0, v1));
            mx1 = fmaxf(mx1, fmaxf(v2, v3));
        }
    }
    mx0 = fmaxf(mx0, __shfl_xor_sync(0xffffffffu, mx0, 1));
    mx0 = fmaxf(mx0, __shfl_xor_sync(0xffffffffu, mx0, 2));
    mx1 = fmaxf(mx1, __shfl_xor_sync(0xffffffffu, mx1, 1));
    mx1 = fmaxf(mx1, __shfl_xor_sync(0xffffffffu, mx1, 2));
    if (tg == 0) {
        smf[PMX + half * 128 + r0] = mx0;
        smf[PMX + half * 128 + r1] = mx1;
    }
    BARP(barid);
    mx0 = fmaxf(smf[PMX + r0], smf[PMX + 128 + r0]);
    mx1 = fmaxf(smf[PMX + r1], smf[PMX + 128 + r1]);

    float s0 = 0.f, s1 = 0.f;
    #pragma unroll
    for (int j = 0; j < 8; j++) {
        if (j <= tt) {
            float p0 = __expf(sacc[j][0] - mx0);
            float p1 = __expf(sacc[j][1] - mx0);
            float p2 = __expf(sacc[j][2] - mx1);
            float p3 = __expf(sacc[j][3] - mx1);
            sacc[j][0] = p0; sacc[j][1] = p1; sacc[j][2] = p2; sacc[j][3] = p3;
            s0 += p0 + p1;  s1 += p2 + p3;
        }
    }
    s0 += __shfl_xor_sync(0xffffffffu, s0, 1);
    s0 += __shfl_xor_sync(0xffffffffu, s0, 2);
    s1 += __shfl_xor_sync(0xffffffffu, s1, 1);
    s1 += __shfl_xor_sync(0xffffffffu, s1, 2);
    if (tg == 0) {
        smf[PSUM + half * 128 + r0] = s0;
        smf[PSUM + half * 128 + r1] = s1;
    }
    BARP(barid);
    const float i0 = 1.0f / (smf[PSUM + r0] + smf[PSUM + 128 + r0]);
    const float i1 = 1.0f / (smf[PSUM + r1] + smf[PSUM + 128 + r1]);
    #pragma unroll
    for (int j = 0; j < 8; j++) {
        if (j <= tt) {
            sacc[j][0] *= i0; sacc[j][1] *= i0;
            sacc[j][2] *= i1; sacc[j][3] *= i1;
        }
    }

    // ---- PV: k16 over fused s-tile pairs; B via ldmatrix.trans ----
    float oacc[8][4];
    #pragma unroll
    for (int ht = 0; ht < 8; ht++)
        #pragma unroll
        for (int i = 0; i < 4; i++) oacc[ht][i] = 0.f;

    #pragma unroll
    for (int jj = 0; jj < 4; jj++) {
        int j0 = 2 * jj, j1 = 2 * jj + 1;
        if (j0 <= tt) {
            uint32_t p0h, p0l, p1h, p1l;
            splith(sacc[j0][0], sacc[j0][1], p0h, p0l);
            splith(sacc[j0][2], sacc[j0][3], p1h, p1l);
            if (j1 <= tt) {
                uint32_t q0h, q0l, q1h, q1l;
                splith(sacc[j1][0], sacc[j1][1], q0h, q0l);
                splith(sacc[j1][2], sacc[j1][3], q1h, q1l);
                uint32_t Ph[4] = {p0h, p1h, q0h, q1h};
                uint32_t Pl[4] = {p0l, p1l, q0l, q1l};
                #pragma unroll
                for (int hp = 0; hp < 4; hp++) {
                    uint32_t VH[4], VL[4];
                    LDM4T(VH, sb + AV_H * 4 + v_byte + jj * 4608 + hp * 32);
                    LDM4T(VL, sb + AV_L * 4 + v_byte + jj * 4608 + hp * 32);
                    mma_f16(oacc[2*hp],   Ph, VH[0], VH[1]);
                    mma_f16(oacc[2*hp+1], Ph, VH[2], VH[3]);
                    mma_f16(oacc[2*hp],   Ph, VL[0], VL[1]);
                    mma_f16(oacc[2*hp+1], Ph, VL[2], VL[3]);
                    mma_f16(oacc[2*hp],   Pl, VH[0], VH[1]);
                    mma_f16(oacc[2*hp+1], Pl, VH[2], VH[3]);
                }
            } else {
                #pragma unroll
                for (int hp = 0; hp < 4; hp++) {
                    uint32_t VH[4], VL[4];
                    LDM4T(VH, sb + AV_H * 4 + v_byte + jj * 4608 + hp * 32);
                    LDM4T(VL, sb + AV_L * 4 + v_byte + jj * 4608 + hp * 32);
                    mma_f16_k8(oacc[2*hp],   p0h, p1h, VH[0]);
                    mma_f16_k8(oacc[2*hp+1], p0h, p1h, VH[2]);
                    mma_f16_k8(oacc[2*hp],   p0h, p1h, VL[0]);
                    mma_f16_k8(oacc[2*hp+1], p0h, p1h, VL[2]);
                    mma_f16_k8(oacc[2*hp],   p0l, p1l, VH[0]);
                    mma_f16_k8(oacc[2*hp+1], p0l, p1l, VH[2]);
                }
            }
        }
    }

    if (half) {
        #pragma unroll
        for (int ht = 0; ht < 8; ht++) {
            int c = ht * 8 + 2 * tg;
            *(float2*)&smf[OPART + r0 * 66 + c] = make_float2(oacc[ht][0], oacc[ht][1]);
            *(float2*)&smf[OPART + r1 * 66 + c] = make_float2(oacc[ht][2], oacc[ht][3]);
        }
    }
    BARP(barid);
    if (!half) {
        float* ob = out + (size_t)b * TQ * HD;
        #pragma unroll
        for (int ht = 0; ht < 8; ht++) {
            int c = ht * 8 + 2 * tg;
            float2 q0 = *(float2*)&smf[OPART + r0 * 66 + c];
            float2 q1 = *(float2*)&smf[OPART + r1 * 66 + c];
            *(float2*)(ob + (size_t)r0 * HD + c) =
                make_float2(oacc[ht][0] + q0.x, oacc[ht][1] + q0.y);
            *(float2*)(ob + (size_t)r1 * HD + c) =
                make_float2(oacc[ht][2] + q1.x, oacc[ht][3] + q1.y);
        }
    }
}

// ============================================================================
extern "C" void kernel_launch(void* const* d_in, const int* in_sizes, int n_in,
                              void* d_out, int out_size)
{
    (void)in_sizes; (void)n_in; (void)out_size;
    const float* x  = (const float*)d_in[0];
    const float* Wq = (const float*)d_in[1];
    const float* Wk = (const float*)d_in[2];
    const float* Wv = (const float*)d_in[3];
    float* out = (float*)d_out;

    cudaFuncSetAttribute(fused_kernel,
                         cudaFuncAttributeMaxDynamicSharedMemorySize, FU_SMEM);

    wsplit_kernel<<<(192 * 192 + 255) / 256, 256>>>(Wq, Wk, Wv);
    fused_kernel<<<NB, 512, FU_SMEM>>>(x, out);
}

// round 13
// speedup vs baseline: 1.1138x; 1.1138x over previous
#include <cuda_runtime.h>
#include <cuda_fp16.h>
#include <cstdint>

// Problem dims
#define NB   512
#define TQ   128
#define CD   384
#define HD   64
#define SCALE 0.4082482904638631f   // 6^-0.5

// W pre-split: fp16 hi/lo pair words, layout [n=192][kpair=192]
__device__ __align__(16) uint32_t g_whi[192*192];
__device__ __align__(16) uint32_t g_wlo[192*192];

// ---------------- helpers ----------------
__device__ __forceinline__ void mma_f16(float* d, const uint32_t* a,
                                        uint32_t b0, uint32_t b1)
{
    asm("mma.sync.aligned.m16n8k16.row.col.f32.f16.f16.f32 "
        "{%0,%1,%2,%3}, {%4,%5,%6,%7}, {%8,%9}, {%0,%1,%2,%3};"
        : "+f"(d[0]), "+f"(d[1]), "+f"(d[2]), "+f"(d[3])
        : "r"(a[0]), "r"(a[1]), "r"(a[2]), "r"(a[3]), "r"(b0), "r"(b1));
}
__device__ __forceinline__ void mma_f16_k8(float* d, uint32_t a0, uint32_t a1,
                                           uint32_t b0)
{
    asm("mma.sync.aligned.m16n8k8.row.col.f32.f16.f16.f32 "
        "{%0,%1,%2,%3}, {%4,%5}, {%6}, {%0,%1,%2,%3};"
        : "+f"(d[0]), "+f"(d[1]), "+f"(d[2]), "+f"(d[3])
        : "r"(a0), "r"(a1), "r"(b0));
}
#define LDM4(r, a) \
    asm volatile("ldmatrix.sync.aligned.m8n8.x4.shared.b16 {%0,%1,%2,%3}, [%4];" \
        : "=r"((r)[0]), "=r"((r)[1]), "=r"((r)[2]), "=r"((r)[3]) : "r"(a))
#define LDM4T(r, a) \
    asm volatile("ldmatrix.sync.aligned.m8n8.x4.trans.shared.b16 {%0,%1,%2,%3}, [%4];" \
        : "=r"((r)[0]), "=r"((r)[1]), "=r"((r)[2]), "=r"((r)[3]) : "r"(a))
#define BARP(id) asm volatile("bar.sync %0, 64;" :: "r"(id) : "memory")

__device__ __forceinline__ void splith(float e0, float e1,
                                       uint32_t& h, uint32_t& l)
{
    __half2 H = __floats2half2_rn(e0, e1);
    float f0 = __low2float(H), f1 = __high2float(H);
    __half2 L = __floats2half2_rn(e0 - f0, e1 - f1);
    h = *(uint32_t*)&H;
    l = *(uint32_t*)&L;
}
__device__ __forceinline__ void cp16(uint32_t s, const void* g) {
    asm volatile("cp.async.cg.shared.global [%0], [%1], 16;" :: "r"(s), "l"(g));
}

// ============================================================================
// Kernel 0: split W -> fp16 hi/lo pair words, [n=192][kpair=192]
// Mapping: consecutive threads -> consecutive kp => COALESCED WRITES.
// Reads stride 512B but W (294KB) is L2-resident; sectors reused 8x.
// ============================================================================
__global__ __launch_bounds__(256) void wsplit_kernel(
    const float* __restrict__ Wq, const float* __restrict__ Wk,
    const float* __restrict__ Wv)
{
    int idx = blockIdx.x * 256 + threadIdx.x;
    if (idx >= 192 * 192) return;
    int n = idx / 192, kp = idx % 192;        // kp fastest -> coalesced writes
    const float* W = (n < 64) ? Wq : (n < 128) ? Wk : Wv;
    int c = n & 63;
    float e0 = W[(size_t)(2 * kp) * HD + c];
    float e1 = W[(size_t)(2 * kp + 1) * HD + c];
    uint32_t h, l;
    splith(e0, e1, h, l);
    g_whi[idx] = h;
    g_wlo[idx] = l;
}

// ============================================================================
// Fused kernel: one CTA per batch (512 threads, 16 warps).  (R9 structure)
// All Q/K/V tiles stored row-major [row][pair-word], stride 36 words.
// ============================================================================
// smem word offsets
#define PA_H  0          // [2][128*20]
#define PA_L  5120
#define PB_H  10240      // [2][192*20]
#define PB_L  17920
#define AQ_H  25600      // [128][36] each
#define AQ_L  30208
#define AK_H  34816
#define AK_L  39424
#define AV_H  44032
#define AV_L  48640
// overlaid on dead proj buffers:
#define PMX   0          // float [2][128]
#define PSUM  256        // float [2][128]
#define OPART 512        // float [128][66]
#define FU_SMEM (53248 * 4)   // 212,992 B

__global__ __launch_bounds__(512) void fused_kernel(
    const float* __restrict__ x, float* __restrict__ out)
{
    extern __shared__ uint32_t sw[];
    float* smf = (float*)sw;
    const uint32_t sb = (uint32_t)__cvta_generic_to_shared(sw);
    const int tid = threadIdx.x, b = blockIdx.x;
    const int lane = tid & 31, wid = tid >> 5;
    const int gr = lane >> 2, tg = lane & 3;

    // ------------------------- Phase 1: projection -------------------------
    const int arow = tid >> 2;
    const int kw   = (tid & 3) * 4;
    const float* ag = x + ((size_t)b * 128 + arow) * CD + (tid & 3) * 8;

    const uint32_t* bl_src[3];
    uint32_t bl_dstw[3];
    #pragma unroll
    for (int j = 0; j < 3; j++) {
        int id = tid + j * 512;
        int hi = (id < 768);
        int i = hi ? id : id - 768;
        int bn = i >> 2, bch = i & 3;
        bl_src[j] = (hi ? g_whi : g_wlo) + bn * 192 + bch * 4;
        bl_dstw[j] = (hi ? PB_H : PB_L) + bn * 20 + bch * 4;
    }
#define PLOADB(buf, t) do {                                                    \
    _Pragma("unroll")                                                          \
    for (int _j = 0; _j < 3; _j++)                                             \
        cp16(sb + (bl_dstw[_j] + (buf) * 3840) * 4, bl_src[_j] + (t) * 16);    \
    asm volatile("cp.async.commit_group;" ::: "memory");                       \
} while (0)

#define STOREA(buf, r0v, r1v) do {                                             \
    uint32_t _h0,_l0,_h1,_l1,_h2,_l2,_h3,_l3;                                  \
    splith((r0v).x, (r0v).y, _h0, _l0); splith((r0v).z, (r0v).w, _h1, _l1);    \
    splith((r1v).x, (r1v).y, _h2, _l2); splith((r1v).z, (r1v).w, _h3, _l3);    \
    uint32_t* _pH = sw + PA_H + (buf) * 2560 + arow * 20 + kw;                 \
    uint32_t* _pL = sw + PA_L + (buf) * 2560 + arow * 20 + kw;                 \
    *(uint2*)_pH = make_uint2(_h0, _h1); *(uint2*)(_pH + 2) = make_uint2(_h2, _h3); \
    *(uint2*)_pL = make_uint2(_l0, _l1); *(uint2*)(_pL + 2) = make_uint2(_l2, _l3); \
} while (0)

    const int wm = (wid & 3) * 32;
    const int wn = (wid >> 2) * 48;

    const int a_r = (lane & 7) + ((lane >> 3) & 1) * 8;
    const int a_c = ((lane >> 4) & 1) * 4;
    const uint32_t aoff0 = ((wm + a_r) * 20 + a_c) * 4;
    const uint32_t aoff1 = ((wm + 16 + a_r) * 20 + a_c) * 4;
    const int b_r = lane & 7;
    const int b_half = (lane >> 3) & 1;
    const int b_nt = (lane >> 4) & 1;
    uint32_t boff[3];
    #pragma unroll
    for (int p = 0; p < 3; p++)
        boff[p] = ((wn + (2 * p + b_nt) * 8 + b_r) * 20 + b_half * 4) * 4;

    float acc[2][6][4];
    #pragma unroll
    for (int mt = 0; mt < 2; mt++)
        #pragma unroll
        for (int nt = 0; nt < 6; nt++)
            #pragma unroll
            for (int i = 0; i < 4; i++) acc[mt][nt][i] = 0.f;

    float4 ar0 = *(const float4*)ag;
    float4 ar1 = *(const float4*)(ag + 4);
    STOREA(0, ar0, ar1);
    PLOADB(0, 0);
    ar0 = *(const float4*)(ag + 32);
    ar1 = *(const float4*)(ag + 36);

    #pragma unroll 2
    for (int t = 0; t < 12; t++) {
        const int buf = t & 1;
        asm volatile("cp.async.wait_group 0;" ::: "memory");
        __syncthreads();
        if (t < 11) {
            PLOADB(buf ^ 1, t + 1);       // cp.async first (independent)
            STOREA(buf ^ 1, ar0, ar1);    // then the register-split stores
            if (t < 10) {
                ar0 = *(const float4*)(ag + (t + 2) * 32);
                ar1 = *(const float4*)(ag + (t + 2) * 32 + 4);
            }
        }
        const uint32_t aBH = sb + (PA_H + buf * 2560) * 4;
        const uint32_t aBL = sb + (PA_L + buf * 2560) * 4;
        const uint32_t bBH = sb + (PB_H + buf * 3840) * 4;
        const uint32_t bBL = sb + (PB_L + buf * 3840) * 4;
        #pragma unroll
        for (int kk = 0; kk < 2; kk++) {
            uint32_t AH0[4], AH1[4], AL0[4], AL1[4];
            LDM4(AH0, aBH + aoff0 + kk * 32);
            LDM4(AH1, aBH + aoff1 + kk * 32);
            LDM4(AL0, aBL + aoff0 + kk * 32);
            LDM4(AL1, aBL + aoff1 + kk * 32);
            #pragma unroll
            for (int p = 0; p < 3; p++) {
                uint32_t BH[4], BL[4];
                LDM4(BH, bBH + boff[p] + kk * 32);
                LDM4(BL, bBL + boff[p] + kk * 32);
                mma_f16(acc[0][2*p],   AH0, BH[0], BH[1]);
                mma_f16(acc[1][2*p],   AH1, BH[0], BH[1]);
                mma_f16(acc[0][2*p+1], AH0, BH[2], BH[3]);
                mma_f16(acc[1][2*p+1], AH1, BH[2], BH[3]);
                mma_f16(acc[0][2*p],   AH0, BL[0], BL[1]);
                mma_f16(acc[1][2*p],   AH1, BL[0], BL[1]);
                mma_f16(acc[0][2*p+1], AH0, BL[2], BL[3]);
                mma_f16(acc[1][2*p+1], AH1, BL[2], BL[3]);
                mma_f16(acc[0][2*p],   AL0, BH[0], BH[1]);
                mma_f16(acc[1][2*p],   AL1, BH[0], BH[1]);
                mma_f16(acc[0][2*p+1], AL0, BH[2], BH[3]);
                mma_f16(acc[1][2*p+1], AL1, BH[2], BH[3]);
            }
        }
    }

    // ---- proj epilogue: write Q (xSCALE) / K / V into attn smem ----
    #pragma unroll
    for (int nt = 0; nt < 6; nt++) {
        int n = wn + nt * 8;
        int base_h = (n < 64) ? AQ_H : (n < 128) ? AK_H : AV_H;
        int base_l = (n < 64) ? AQ_L : (n < 128) ? AK_L : AV_L;
        float sc = (n < 64) ? SCALE : 1.0f;
        int pidx = ((n & 63) >> 1) + tg;
        #pragma unroll
        for (int mt = 0; mt < 2; mt++) {
            int ra = wm + mt * 16 + gr;
            int rb = ra + 8;
            uint32_t h, l;
            splith(acc[mt][nt][0] * sc, acc[mt][nt][1] * sc, h, l);
            sw[base_h + ra * 36 + pidx] = h;
            sw[base_l + ra * 36 + pidx] = l;
            splith(acc[mt][nt][2] * sc, acc[mt][nt][3] * sc, h, l);
            sw[base_h + rb * 36 + pidx] = h;
            sw[base_l + rb * 36 + pidx] = l;
        }
    }
    __syncthreads();

    // ------------------------- Phase 2: attention (R9) -------------------------
    const int pairIdx = wid & 7;
    const int half = wid >> 3;
    const int tt = (pairIdx < 4) ? pairIdx : 11 - pairIdx;
    const int t0 = 16 * tt;
    const int r0 = t0 + gr, r1 = r0 + 8;
    const int barid = 1 + pairIdx;

    const uint32_t q_byte = ((t0 + a_r) * 36 + a_c) * 4;
    const uint32_t k_byte = (((half + 2 * b_nt) * 8 + b_r) * 36 + 4 * b_half) * 4;
    const int vg = lane >> 3;
    const uint32_t v_byte = (((half + 2 * (vg & 1)) * 8 + (lane & 7)) * 36
                             + ((vg >> 1) ? 4 : 0)) * 4;

    float sacc[8][4];
    #pragma unroll
    for (int j = 0; j < 8; j++)
        #pragma unroll
        for (int i = 0; i < 4; i++) sacc[j][i] = 0.f;

    #pragma unroll
    for (int kk = 0; kk < 4; kk++) {
        uint32_t AH[4], AL[4];
        LDM4(AH, sb + AQ_H * 4 + q_byte + kk * 32);
        LDM4(AL, sb + AQ_L * 4 + q_byte + kk * 32);
        #pragma unroll
        for (int jp = 0; jp < 4; jp++) {
            int j0 = 2 * jp, j1 = 2 * jp + 1;
            if (j0 <= tt) {
                uint32_t KH[4], KL[4];
                LDM4(KH, sb + AK_H * 4 + k_byte + jp * 4608 + kk * 32);
                LDM4(KL, sb + AK_L * 4 + k_byte + jp * 4608 + kk * 32);
                mma_f16(sacc[j0], AH, KH[0], KH[1]);
                mma_f16(sacc[j0], AH, KL[0], KL[1]);
                mma_f16(sacc[j0], AL, KH[0], KH[1]);
                if (j1 <= tt) {
                    mma_f16(sacc[j1], AH, KH[2], KH[3]);
                    mma_f16(sacc[j1], AH, KL[2], KL[3]);
                    mma_f16(sacc[j1], AL, KH[2], KH[3]);
                }
            }
        }
    }

    const float NEG = __int_as_float(0xff800000);
    float mx0 = NEG, mx1 = NEG;
    #pragma unroll
    for (int j = 0; j < 8; j++) {
        if (j <= tt) {
            int c = (2 * j + half) * 8 + 2 * tg;
            float v0 = (c     <= r0) ? sacc[j][0] : NEG;   // SCALE already in Q
            float v1 = (c + 1 <= r0) ? sacc[j][1] : NEG;
            float v2 = (c     <= r1) ? sacc[j][2] : NEG;
            float v3 = (c + 1 <= r1) ? sacc[j][3] : NEG;
            sacc[j][0] = v0; sacc[j][1] = v1; sacc[j][2] = v2; sacc[j][3] = v3;
            mx0 = fmaxf(mx0, fmaxf(v0, v1));
            mx1 = fmaxf(mx1, fmaxf(v2, v3));
        }
    }
    mx0 = fmaxf(mx0, __shfl_xor_sync(0xffffffffu, mx0, 1));
    mx0 = fmaxf(mx0, __shfl_xor_sync(0xffffffffu, mx0, 2));
    mx1 = fmaxf(mx1, __shfl_xor_sync(0xffffffffu, mx1, 1));
    mx1 = fmaxf(mx1, __shfl_xor_sync(0xffffffffu, mx1, 2));
    if (tg == 0) {
        smf[PMX + half * 128 + r0] = mx0;
        smf[PMX + half * 128 + r1] = mx1;
    }
    BARP(barid);
    mx0 = fmaxf(smf[PMX + r0], smf[PMX + 128 + r0]);
    mx1 = fmaxf(smf[PMX + r1], smf[PMX + 128 + r1]);

    float s0 = 0.f, s1 = 0.f;
    #pragma unroll
    for (int j = 0; j < 8; j++) {
        if (j <= tt) {
            float p0 = __expf(sacc[j][0] - mx0);
            float p1 = __expf(sacc[j][1] - mx0);
            float p2 = __expf(sacc[j][2] - mx1);
            float p3 = __expf(sacc[j][3] - mx1);
            sacc[j][0] = p0; sacc[j][1] = p1; sacc[j][2] = p2; sacc[j][3] = p3;
            s0 += p0 + p1;  s1 += p2 + p3;
        }
    }
    s0 += __shfl_xor_sync(0xffffffffu, s0, 1);
    s0 += __shfl_xor_sync(0xffffffffu, s0, 2);
    s1 += __shfl_xor_sync(0xffffffffu, s1, 1);
    s1 += __shfl_xor_sync(0xffffffffu, s1, 2);
    if (tg == 0) {
        smf[PSUM + half * 128 + r0] = s0;
        smf[PSUM + half * 128 + r1] = s1;
    }
    BARP(barid);
    const float i0 = 1.0f / (smf[PSUM + r0] + smf[PSUM + 128 + r0]);
    const float i1 = 1.0f / (smf[PSUM + r1] + smf[PSUM + 128 + r1]);
    #pragma unroll
    for (int j = 0; j < 8; j++) {
        if (j <= tt) {
            sacc[j][0] *= i0; sacc[j][1] *= i0;
            sacc[j][2] *= i1; sacc[j][3] *= i1;
        }
    }

    // ---- PV: k16 over fused s-tile pairs; B via ldmatrix.trans ----
    float oacc[8][4];
    #pragma unroll
    for (int ht = 0; ht < 8; ht++)
        #pragma unroll
        for (int i = 0; i < 4; i++) oacc[ht][i] = 0.f;

    #pragma unroll
    for (int jj = 0; jj < 4; jj++) {
        int j0 = 2 * jj, j1 = 2 * jj + 1;
        if (j0 <= tt) {
            uint32_t p0h, p0l, p1h, p1l;
            splith(sacc[j0][0], sacc[j0][1], p0h, p0l);
            splith(sacc[j0][2], sacc[j0][3], p1h, p1l);
            if (j1 <= tt) {
                uint32_t q0h, q0l, q1h, q1l;
                splith(sacc[j1][0], sacc[j1][1], q0h, q0l);
                splith(sacc[j1][2], sacc[j1][3], q1h, q1l);
                uint32_t Ph[4] = {p0h, p1h, q0h, q1h};
                uint32_t Pl[4] = {p0l, p1l, q0l, q1l};
                #pragma unroll
                for (int hp = 0; hp < 4; hp++) {
                    uint32_t VH[4], VL[4];
                    LDM4T(VH, sb + AV_H * 4 + v_byte + jj * 4608 + hp * 32);
                    LDM4T(VL, sb + AV_L * 4 + v_byte + jj * 4608 + hp * 32);
                    mma_f16(oacc[2*hp],   Ph, VH[0], VH[1]);
                    mma_f16(oacc[2*hp+1], Ph, VH[2], VH[3]);
                    mma_f16(oacc[2*hp],   Ph, VL[0], VL[1]);
                    mma_f16(oacc[2*hp+1], Ph, VL[2], VL[3]);
                    mma_f16(oacc[2*hp],   Pl, VH[0], VH[1]);
                    mma_f16(oacc[2*hp+1], Pl, VH[2], VH[3]);
                }
            } else {
                #pragma unroll
                for (int hp = 0; hp < 4; hp++) {
                    uint32_t VH[4], VL[4];
                    LDM4T(VH, sb + AV_H * 4 + v_byte + jj * 4608 + hp * 32);
                    LDM4T(VL, sb + AV_L * 4 + v_byte + jj * 4608 + hp * 32);
                    mma_f16_k8(oacc[2*hp],   p0h, p1h, VH[0]);
                    mma_f16_k8(oacc[2*hp+1], p0h, p1h, VH[2]);
                    mma_f16_k8(oacc[2*hp],   p0h, p1h, VL[0]);
                    mma_f16_k8(oacc[2*hp+1], p0h, p1h, VL[2]);
                    mma_f16_k8(oacc[2*hp],   p0l, p1l, VH[0]);
                    mma_f16_k8(oacc[2*hp+1], p0l, p1l, VH[2]);
                }
            }
        }
    }

    if (half) {
        #pragma unroll
        for (int ht = 0; ht < 8; ht++) {
            int c = ht * 8 + 2 * tg;
            *(float2*)&smf[OPART + r0 * 66 + c] = make_float2(oacc[ht][0], oacc[ht][1]);
            *(float2*)&smf[OPART + r1 * 66 + c] = make_float2(oacc[ht][2], oacc[ht][3]);
        }
    }
    BARP(barid);
    if (!half) {
        float* ob = out + (size_t)b * TQ * HD;
        #pragma unroll
        for (int ht = 0; ht < 8; ht++) {
            int c = ht * 8 + 2 * tg;
            float2 q0 = *(float2*)&smf[OPART + r0 * 66 + c];
            float2 q1 = *(float2*)&smf[OPART + r1 * 66 + c];
            *(float2*)(ob + (size_t)r0 * HD + c) =
                make_float2(oacc[ht][0] + q0.x, oacc[ht][1] + q0.y);
            *(float2*)(ob + (size_t)r1 * HD + c) =
                make_float2(oacc[ht][2] + q1.x, oacc[ht][3] + q1.y);
        }
    }
}

// ============================================================================
extern "C" void kernel_launch(void* const* d_in, const int* in_sizes, int n_in,
                              void* d_out, int out_size)
{
    (void)in_sizes; (void)n_in; (void)out_size;
    const float* x  = (const float*)d_in[0];
    const float* Wq = (const float*)d_in[1];
    const float* Wk = (const float*)d_in[2];
    const float* Wv = (const float*)d_in[3];
    float* out = (float*)d_out;

    cudaFuncSetAttribute(fused_kernel,
                         cudaFuncAttributeMaxDynamicSharedMemorySize, FU_SMEM);

    wsplit_kernel<<<(192 * 192 + 255) / 256, 256>>>(Wq, Wk, Wv);
    fused_kernel<<<NB, 512, FU_SMEM>>>(x, out);
}

// round 14
// speedup vs baseline: 1.2483x; 1.1208x over previous
#include <cuda_runtime.h>
#include <cuda_fp16.h>
#include <cstdint>

// Problem dims
#define NB   512
#define TQ   128
#define CD   384
#define HD   64
#define SCALE 0.4082482904638631f   // 6^-0.5

// W pre-split: fp16 hi/lo pair words, layout [n=192][kpair=192]
__device__ __align__(16) uint32_t g_whi[192*192];
__device__ __align__(16) uint32_t g_wlo[192*192];

// ---------------- helpers ----------------
__device__ __forceinline__ void mma_f16(float* d, const uint32_t* a,
                                        uint32_t b0, uint32_t b1)
{
    asm("mma.sync.aligned.m16n8k16.row.col.f32.f16.f16.f32 "
        "{%0,%1,%2,%3}, {%4,%5,%6,%7}, {%8,%9}, {%0,%1,%2,%3};"
        : "+f"(d[0]), "+f"(d[1]), "+f"(d[2]), "+f"(d[3])
        : "r"(a[0]), "r"(a[1]), "r"(a[2]), "r"(a[3]), "r"(b0), "r"(b1));
}
__device__ __forceinline__ void mma_f16_k8(float* d, uint32_t a0, uint32_t a1,
                                           uint32_t b0)
{
    asm("mma.sync.aligned.m16n8k8.row.col.f32.f16.f16.f32 "
        "{%0,%1,%2,%3}, {%4,%5}, {%6}, {%0,%1,%2,%3};"
        : "+f"(d[0]), "+f"(d[1]), "+f"(d[2]), "+f"(d[3])
        : "r"(a0), "r"(a1), "r"(b0));
}
#define LDM4(r, a) \
    asm volatile("ldmatrix.sync.aligned.m8n8.x4.shared.b16 {%0,%1,%2,%3}, [%4];" \
        : "=r"((r)[0]), "=r"((r)[1]), "=r"((r)[2]), "=r"((r)[3]) : "r"(a))
#define LDM4T(r, a) \
    asm volatile("ldmatrix.sync.aligned.m8n8.x4.trans.shared.b16 {%0,%1,%2,%3}, [%4];" \
        : "=r"((r)[0]), "=r"((r)[1]), "=r"((r)[2]), "=r"((r)[3]) : "r"(a))
#define BARP(id) asm volatile("bar.sync %0, 64;" :: "r"(id) : "memory")

__device__ __forceinline__ void splith(float e0, float e1,
                                       uint32_t& h, uint32_t& l)
{
    __half2 H = __floats2half2_rn(e0, e1);
    float f0 = __low2float(H), f1 = __high2float(H);
    __half2 L = __floats2half2_rn(e0 - f0, e1 - f1);
    h = *(uint32_t*)&H;
    l = *(uint32_t*)&L;
}
__device__ __forceinline__ void cp16(uint32_t s, const void* g) {
    asm volatile("cp.async.cg.shared.global [%0], [%1], 16;" :: "r"(s), "l"(g));
}

// ============================================================================
// Kernel 0: split W -> fp16 hi/lo pair words, [n=192][kpair=192]
// ============================================================================
__global__ __launch_bounds__(256) void wsplit_kernel(
    const float* __restrict__ Wq, const float* __restrict__ Wk,
    const float* __restrict__ Wv)
{
    int idx = blockIdx.x * 256 + threadIdx.x;
    if (idx >= 192 * 192) return;
    int kp = idx / 192, n = idx % 192;        // n fastest -> coalesced reads
    const float* W = (n < 64) ? Wq : (n < 128) ? Wk : Wv;
    int c = n & 63;
    float e0 = W[(size_t)(2 * kp) * HD + c];
    float e1 = W[(size_t)(2 * kp + 1) * HD + c];
    uint32_t h, l;
    splith(e0, e1, h, l);
    g_whi[n * 192 + kp] = h;
    g_wlo[n * 192 + kp] = l;
}

// ============================================================================
// Fused kernel: one CTA per batch (512 threads, 16 warps).
// All Q/K/V tiles stored row-major [row][pair-word], stride 36 words.
// ============================================================================
// smem word offsets
#define PA_H  0          // [2][128*20]
#define PA_L  5120
#define PB_H  10240      // [2][192*20]
#define PB_L  17920
#define AQ_H  25600      // [128][36] each
#define AQ_L  30208
#define AK_H  34816
#define AK_L  39424
#define AV_H  44032
#define AV_L  48640
// overlaid on dead proj buffers:
#define PMX   0          // float [2][128]
#define PSUM  256        // float [2][128]
#define OPART 512        // float [128][66]
#define FU_SMEM (53248 * 4)   // 212,992 B

__global__ __launch_bounds__(512) void fused_kernel(
    const float* __restrict__ x, float* __restrict__ out)
{
    extern __shared__ uint32_t sw[];
    float* smf = (float*)sw;
    const uint32_t sb = (uint32_t)__cvta_generic_to_shared(sw);
    const int tid = threadIdx.x, b = blockIdx.x;
    const int lane = tid & 31, wid = tid >> 5;
    const int gr = lane >> 2, tg = lane & 3;

    // ------------------------- Phase 1: projection -------------------------
    const int arow = tid >> 2;
    const int kw   = (tid & 3) * 4;
    const float* ag = x + ((size_t)b * 128 + arow) * CD + (tid & 3) * 8;

    const uint32_t* bl_src[3];
    uint32_t bl_dstw[3];
    #pragma unroll
    for (int j = 0; j < 3; j++) {
        int id = tid + j * 512;
        int hi = (id < 768);
        int i = hi ? id : id - 768;
        int bn = i >> 2, bch = i & 3;
        bl_src[j] = (hi ? g_whi : g_wlo) + bn * 192 + bch * 4;
        bl_dstw[j] = (hi ? PB_H : PB_L) + bn * 20 + bch * 4;
    }
#define PLOADB(buf, t) do {                                                    \
    _Pragma("unroll")                                                          \
    for (int _j = 0; _j < 3; _j++)                                             \
        cp16(sb + (bl_dstw[_j] + (buf) * 3840) * 4, bl_src[_j] + (t) * 16);    \
    asm volatile("cp.async.commit_group;" ::: "memory");                       \
} while (0)

#define STOREA(buf, r0v, r1v) do {                                             \
    uint32_t _h0,_l0,_h1,_l1,_h2,_l2,_h3,_l3;                                  \
    splith((r0v).x, (r0v).y, _h0, _l0); splith((r0v).z, (r0v).w, _h1, _l1);    \
    splith((r1v).x, (r1v).y, _h2, _l2); splith((r1v).z, (r1v).w, _h3, _l3);    \
    uint32_t* _pH = sw + PA_H + (buf) * 2560 + arow * 20 + kw;                 \
    uint32_t* _pL = sw + PA_L + (buf) * 2560 + arow * 20 + kw;                 \
    *(uint2*)_pH = make_uint2(_h0, _h1); *(uint2*)(_pH + 2) = make_uint2(_h2, _h3); \
    *(uint2*)_pL = make_uint2(_l0, _l1); *(uint2*)(_pL + 2) = make_uint2(_l2, _l3); \
} while (0)

    const int wm = (wid & 3) * 32;
    const int wn = (wid >> 2) * 48;

    const int a_r = (lane & 7) + ((lane >> 3) & 1) * 8;
    const int a_c = ((lane >> 4) & 1) * 4;
    const uint32_t aoff0 = ((wm + a_r) * 20 + a_c) * 4;
    const uint32_t aoff1 = ((wm + 16 + a_r) * 20 + a_c) * 4;
    const int b_r = lane & 7;
    const int b_half = (lane >> 3) & 1;
    const int b_nt = (lane >> 4) & 1;
    uint32_t boff[3];
    #pragma unroll
    for (int p = 0; p < 3; p++)
        boff[p] = ((wn + (2 * p + b_nt) * 8 + b_r) * 20 + b_half * 4) * 4;

    float acc[2][6][4];
    #pragma unroll
    for (int mt = 0; mt < 2; mt++)
        #pragma unroll
        for (int nt = 0; nt < 6; nt++)
            #pragma unroll
            for (int i = 0; i < 4; i++) acc[mt][nt][i] = 0.f;

    float4 ar0 = *(const float4*)ag;
    float4 ar1 = *(const float4*)(ag + 4);
    STOREA(0, ar0, ar1);
    PLOADB(0, 0);
    ar0 = *(const float4*)(ag + 32);
    ar1 = *(const float4*)(ag + 36);

    #pragma unroll 2
    for (int t = 0; t < 12; t++) {
        const int buf = t & 1;
        asm volatile("cp.async.wait_group 0;" ::: "memory");
        __syncthreads();
        if (t < 11) {
            STOREA(buf ^ 1, ar0, ar1);
            PLOADB(buf ^ 1, t + 1);
            if (t < 10) {
                ar0 = *(const float4*)(ag + (t + 2) * 32);
                ar1 = *(const float4*)(ag + (t + 2) * 32 + 4);
            }
        }
        const uint32_t aBH = sb + (PA_H + buf * 2560) * 4;
        const uint32_t aBL = sb + (PA_L + buf * 2560) * 4;
        const uint32_t bBH = sb + (PB_H + buf * 3840) * 4;
        const uint32_t bBL = sb + (PB_L + buf * 3840) * 4;
        #pragma unroll
        for (int kk = 0; kk < 2; kk++) {
            uint32_t AH0[4], AH1[4], AL0[4], AL1[4];
            LDM4(AH0, aBH + aoff0 + kk * 32);
            LDM4(AH1, aBH + aoff1 + kk * 32);
            LDM4(AL0, aBL + aoff0 + kk * 32);
            LDM4(AL1, aBL + aoff1 + kk * 32);
            #pragma unroll
            for (int p = 0; p < 3; p++) {
                uint32_t BH[4], BL[4];
                LDM4(BH, bBH + boff[p] + kk * 32);
                LDM4(BL, bBL + boff[p] + kk * 32);
                mma_f16(acc[0][2*p],   AH0, BH[0], BH[1]);
                mma_f16(acc[1][2*p],   AH1, BH[0], BH[1]);
                mma_f16(acc[0][2*p+1], AH0, BH[2], BH[3]);
                mma_f16(acc[1][2*p+1], AH1, BH[2], BH[3]);
                mma_f16(acc[0][2*p],   AH0, BL[0], BL[1]);
                mma_f16(acc[1][2*p],   AH1, BL[0], BL[1]);
                mma_f16(acc[0][2*p+1], AH0, BL[2], BL[3]);
                mma_f16(acc[1][2*p+1], AH1, BL[2], BL[3]);
                mma_f16(acc[0][2*p],   AL0, BH[0], BH[1]);
                mma_f16(acc[1][2*p],   AL1, BH[0], BH[1]);
                mma_f16(acc[0][2*p+1], AL0, BH[2], BH[3]);
                mma_f16(acc[1][2*p+1], AL1, BH[2], BH[3]);
            }
        }
    }

    // ---- proj epilogue: write Q (xSCALE) / K / V into attn smem ----
    #pragma unroll
    for (int nt = 0; nt < 6; nt++) {
        int n = wn + nt * 8;
        int base_h = (n < 64) ? AQ_H : (n < 128) ? AK_H : AV_H;
        int base_l = (n < 64) ? AQ_L : (n < 128) ? AK_L : AV_L;
        float sc = (n < 64) ? SCALE : 1.0f;
        int pidx = ((n & 63) >> 1) + tg;
        #pragma unroll
        for (int mt = 0; mt < 2; mt++) {
            int ra = wm + mt * 16 + gr;
            int rb = ra + 8;
            uint32_t h, l;
            splith(acc[mt][nt][0] * sc, acc[mt][nt][1] * sc, h, l);
            sw[base_h + ra * 36 + pidx] = h;
            sw[base_l + ra * 36 + pidx] = l;
            splith(acc[mt][nt][2] * sc, acc[mt][nt][3] * sc, h, l);
            sw[base_h + rb * 36 + pidx] = h;
            sw[base_l + rb * 36 + pidx] = l;
        }
    }
    __syncthreads();

    // ------------------------- Phase 2: attention -------------------------
    const int pairIdx = wid & 7;
    const int half = wid >> 3;
    const int tt = (pairIdx < 4) ? pairIdx : 11 - pairIdx;
    const int t0 = 16 * tt;
    const int r0 = t0 + gr, r1 = r0 + 8;
    const int barid = 1 + pairIdx;

    const uint32_t q_byte = ((t0 + a_r) * 36 + a_c) * 4;
    const uint32_t k_byte = (((half + 2 * b_nt) * 8 + b_r) * 36 + 4 * b_half) * 4;
    const int vg = lane >> 3;
    const uint32_t v_byte = (((half + 2 * (vg & 1)) * 8 + (lane & 7)) * 36
                             + ((vg >> 1) ? 4 : 0)) * 4;

    float sacc[8][4];
    #pragma unroll
    for (int j = 0; j < 8; j++)
        #pragma unroll
        for (int i = 0; i < 4; i++) sacc[j][i] = 0.f;

    #pragma unroll
    for (int kk = 0; kk < 4; kk++) {
        uint32_t AH[4], AL[4];
        LDM4(AH, sb + AQ_H * 4 + q_byte + kk * 32);
        LDM4(AL, sb + AQ_L * 4 + q_byte + kk * 32);
        #pragma unroll
        for (int jp = 0; jp < 4; jp++) {
            int j0 = 2 * jp, j1 = 2 * jp + 1;
            if (j0 <= tt) {
                uint32_t KH[4], KL[4];
                LDM4(KH, sb + AK_H * 4 + k_byte + jp * 4608 + kk * 32);
                LDM4(KL, sb + AK_L * 4 + k_byte + jp * 4608 + kk * 32);
                mma_f16(sacc[j0], AH, KH[0], KH[1]);
                mma_f16(sacc[j0], AH, KL[0], KL[1]);
                mma_f16(sacc[j0], AL, KH[0], KH[1]);
                if (j1 <= tt) {
                    mma_f16(sacc[j1], AH, KH[2], KH[3]);
                    mma_f16(sacc[j1], AH, KL[2], KL[3]);
                    mma_f16(sacc[j1], AL, KH[2], KH[3]);
                }
            }
        }
    }

    const float NEG = __int_as_float(0xff800000);
    float mx0 = NEG, mx1 = NEG;
    #pragma unroll
    for (int j = 0; j < 8; j++) {
        if (j <= tt) {
            int c = (2 * j + half) * 8 + 2 * tg;
            float v0 = (c     <= r0) ? sacc[j][0] : NEG;   // SCALE already in Q
            float v1 = (c + 1 <= r0) ? sacc[j][1] : NEG;
            float v2 = (c     <= r1) ? sacc[j][2] : NEG;
            float v3 = (c + 1 <= r1) ? sacc[j][3] : NEG;
            sacc[j][0] = v0; sacc[j][1] = v1; sacc[j][2] = v2; sacc[j][3] = v3;
            mx0 = fmaxf(mx0, fmaxf(v0, v1));
            mx1 = fmaxf(mx1, fmaxf(v2, v3));
        }
    }
    mx0 = fmaxf(mx0, __shfl_xor_sync(0xffffffffu, mx0, 1));
    mx0 = fmaxf(mx0, __shfl_xor_sync(0xffffffffu, mx0, 2));
    mx1 = fmaxf(mx1, __shfl_xor_sync(0xffffffffu, mx1, 1));
    mx1 = fmaxf(mx1, __shfl_xor_sync(0xffffffffu, mx1, 2));
    if (tg == 0) {
        smf[PMX + half * 128 + r0] = mx0;
        smf[PMX + half * 128 + r1] = mx1;
    }
    BARP(barid);
    mx0 = fmaxf(smf[PMX + r0], smf[PMX + 128 + r0]);
    mx1 = fmaxf(smf[PMX + r1], smf[PMX + 128 + r1]);

    float s0 = 0.f, s1 = 0.f;
    #pragma unroll
    for (int j = 0; j < 8; j++) {
        if (j <= tt) {
            float p0 = __expf(sacc[j][0] - mx0);
            float p1 = __expf(sacc[j][1] - mx0);
            float p2 = __expf(sacc[j][2] - mx1);
            float p3 = __expf(sacc[j][3] - mx1);
            sacc[j][0] = p0; sacc[j][1] = p1; sacc[j][2] = p2; sacc[j][3] = p3;
            s0 += p0 + p1;  s1 += p2 + p3;
        }
    }
    s0 += __shfl_xor_sync(0xffffffffu, s0, 1);
    s0 += __shfl_xor_sync(0xffffffffu, s0, 2);
    s1 += __shfl_xor_sync(0xffffffffu, s1, 1);
    s1 += __shfl_xor_sync(0xffffffffu, s1, 2);
    if (tg == 0) {
        smf[PSUM + half * 128 + r0] = s0;
        smf[PSUM + half * 128 + r1] = s1;
    }
    BARP(barid);
    const float i0 = 1.0f / (smf[PSUM + r0] + smf[PSUM + 128 + r0]);
    const float i1 = 1.0f / (smf[PSUM + r1] + smf[PSUM + 128 + r1]);
    #pragma unroll
    for (int j = 0; j < 8; j++) {
        if (j <= tt) {
            sacc[j][0] *= i0; sacc[j][1] *= i0;
            sacc[j][2] *= i1; sacc[j][3] *= i1;
        }
    }

    // ---- PV: k16 over fused s-tile pairs; B via ldmatrix.trans ----
    float oacc[8][4];
    #pragma unroll
    for (int ht = 0; ht < 8; ht++)
        #pragma unroll
        for (int i = 0; i < 4; i++) oacc[ht][i] = 0.f;

    #pragma unroll
    for (int jj = 0; jj < 4; jj++) {
        int j0 = 2 * jj, j1 = 2 * jj + 1;
        if (j0 <= tt) {
            uint32_t p0h, p0l, p1h, p1l;
            splith(sacc[j0][0], sacc[j0][1], p0h, p0l);
            splith(sacc[j0][2], sacc[j0][3], p1h, p1l);
            if (j1 <= tt) {
                uint32_t q0h, q0l, q1h, q1l;
                splith(sacc[j1][0], sacc[j1][1], q0h, q0l);
                splith(sacc[j1][2], sacc[j1][3], q1h, q1l);
                uint32_t Ph[4] = {p0h, p1h, q0h, q1h};
                uint32_t Pl[4] = {p0l, p1l, q0l, q1l};
                #pragma unroll
                for (int hp = 0; hp < 4; hp++) {
                    uint32_t VH[4], VL[4];
                    LDM4T(VH, sb + AV_H * 4 + v_byte + jj * 4608 + hp * 32);
                    LDM4T(VL, sb + AV_L * 4 + v_byte + jj * 4608 + hp * 32);
                    mma_f16(oacc[2*hp],   Ph, VH[0], VH[1]);
                    mma_f16(oacc[2*hp+1], Ph, VH[2], VH[3]);
                    mma_f16(oacc[2*hp],   Ph, VL[0], VL[1]);
                    mma_f16(oacc[2*hp+1], Ph, VL[2], VL[3]);
                    mma_f16(oacc[2*hp],   Pl, VH[0], VH[1]);
                    mma_f16(oacc[2*hp+1], Pl, VH[2], VH[3]);
                }
            } else {
                #pragma unroll
                for (int hp = 0; hp < 4; hp++) {
                    uint32_t VH[4], VL[4];
                    LDM4T(VH, sb + AV_H * 4 + v_byte + jj * 4608 + hp * 32);
                    LDM4T(VL, sb + AV_L * 4 + v_byte + jj * 4608 + hp * 32);
                    mma_f16_k8(oacc[2*hp],   p0h, p1h, VH[0]);
                    mma_f16_k8(oacc[2*hp+1], p0h, p1h, VH[2]);
                    mma_f16_k8(oacc[2*hp],   p0h, p1h, VL[0]);
                    mma_f16_k8(oacc[2*hp+1], p0h, p1h, VL[2]);
                    mma_f16_k8(oacc[2*hp],   p0l, p1l, VH[0]);
                    mma_f16_k8(oacc[2*hp+1], p0l, p1l, VH[2]);
                }
            }
        }
    }

    if (half) {
        #pragma unroll
        for (int ht = 0; ht < 8; ht++) {
            int c = ht * 8 + 2 * tg;
            *(float2*)&smf[OPART + r0 * 66 + c] = make_float2(oacc[ht][0], oacc[ht][1]);
            *(float2*)&smf[OPART + r1 * 66 + c] = make_float2(oacc[ht][2], oacc[ht][3]);
        }
    }
    BARP(barid);
    if (!half) {
        float* ob = out + (size_t)b * TQ * HD;
        #pragma unroll
        for (int ht = 0; ht < 8; ht++) {
            int c = ht * 8 + 2 * tg;
            float2 q0 = *(float2*)&smf[OPART + r0 * 66 + c];
            float2 q1 = *(float2*)&smf[OPART + r1 * 66 + c];
            *(float2*)(ob + (size_t)r0 * HD + c) =
                make_float2(oacc[ht][0] + q0.x, oacc[ht][1] + q0.y);
            *(float2*)(ob + (size_t)r1 * HD + c) =
                make_float2(oacc[ht][2] + q1.x, oacc[ht][3] + q1.y);
        }
    }
}

// ============================================================================
extern "C" void kernel_launch(void* const* d_in, const int* in_sizes, int n_in,
                              void* d_out, int out_size)
{
    (void)in_sizes; (void)n_in; (void)out_size;
    const float* x  = (const float*)d_in[0];
    const float* Wq = (const float*)d_in[1];
    const float* Wk = (const float*)d_in[2];
    const float* Wv = (const float*)d_in[3];
    float* out = (float*)d_out;

    cudaFuncSetAttribute(fused_kernel,
                         cudaFuncAttributeMaxDynamicSharedMemorySize, FU_SMEM);

    wsplit_kernel<<<(192 * 192 + 255) / 256, 256>>>(Wq, Wk, Wv);
    fused_kernel<<<NB, 512, FU_SMEM>>>(x, out);
}